// round 4
// baseline (speedup 1.0000x reference)
#include <cuda_runtime.h>
#include <math.h>
#include <float.h>

// Problem constants
#define BB   16      // batch
#define KK   4       // beam
#define RR   64      // BB*KK rows
#define SS   512     // encoder seq
#define DD   512     // model dim
#define VV   32000   // vocab
#define TT   64      // max len
#define SOS_ 1
#define EOS_ 2
#define PAD_ 0
#define NEG_ (-1e9f)

#define NT   (VV / 128)   // 250 N-tiles for logits GEMM

// -------- device state --------
__device__ float g_encK[BB * SS * DD];      // 16.8 MB
__device__ float g_h[RR * DD];
__device__ int   g_seqs[2][RR * TT];
__device__ float g_scores[RR];
__device__ int   g_finished[RR];
__device__ int   g_last[RR];
// per-(row, n-tile) partials from the logits GEMM epilogue
__device__ float g_pv[RR * NT * 4];
__device__ int   g_pi[RR * NT * 4];
__device__ float g_pm[RR * NT];
__device__ float g_ps[RR * NT];

// ---------------- packed f32x2 helpers ----------------
__device__ __forceinline__ void ffma2(unsigned long long& d,
                                      unsigned long long a,
                                      unsigned long long b) {
    asm("fma.rn.f32x2 %0, %1, %2, %0;" : "+l"(d) : "l"(a), "l"(b));
}
__device__ __forceinline__ unsigned long long dup2(float x) {
    unsigned long long r;
    asm("mov.b64 %0, {%1, %1};" : "=l"(r) : "f"(x));
    return r;
}
__device__ __forceinline__ void unpack2(unsigned long long v, float& lo, float& hi) {
    asm("mov.b64 {%0, %1}, %2;" : "=f"(lo), "=f"(hi) : "l"(v));
}

__device__ __forceinline__ bool better_vi(float v1, int i1, float v2, int i2) {
    return (v1 > v2) || (v1 == v2 && i1 < i2);
}
__device__ __forceinline__ void ins4(float x, int c, float* v, int* ix) {
    if (better_vi(x, c, v[3], ix[3])) {
        v[3] = x; ix[3] = c;
#pragma unroll
        for (int p = 3; p > 0; p--) {
            if (better_vi(v[p], ix[p], v[p - 1], ix[p - 1])) {
                float tv = v[p]; v[p] = v[p - 1]; v[p - 1] = tv;
                int ti = ix[p]; ix[p] = ix[p - 1]; ix[p - 1] = ti;
            }
        }
    }
}
// merge sorted-desc 4-list (v2,i2) into (v,ix)
__device__ __forceinline__ void merge4(float* v, int* ix, const float* v2, const int* i2) {
    float ov[4]; int oi[4];
    int pa = 0, pb = 0;
#pragma unroll
    for (int t = 0; t < 4; t++) {
        bool takeA = (pb >= 4) || (pa < 4 && better_vi(v[pa], ix[pa], v2[pb], i2[pb]));
        if (takeA) { ov[t] = v[pa]; oi[t] = ix[pa]; pa++; }
        else       { ov[t] = v2[pb]; oi[t] = i2[pb]; pb++; }
    }
#pragma unroll
    for (int p = 0; p < 4; p++) { v[p] = ov[p]; ix[p] = oi[p]; }
}

// ============ FFMA2 GEMM, tile 64x128, 128 threads ============
// thread: 8 rows (4 packed row-pairs) x 8 cols.
// TOPK=false: writes C (+bias). TOPK=true: per-row top4 + sumexp partials, no C write.
#define GTK 32
#define ASTRIDE 66

template<bool TOPK>
__global__ __launch_bounds__(128) void gemm2_kernel(
    const float* __restrict__ A, const float* __restrict__ B,
    const float* __restrict__ bias, float* __restrict__ C,
    int M, int N, int Kd)
{
    __shared__ __align__(16) float As[GTK][ASTRIDE];
    __shared__ __align__(16) float Bs[GTK][128];
    const int tid = threadIdx.x;
    const int bx = blockIdx.x;
    const int n0 = bx * 128;
    const int m0 = blockIdx.y * 64;
    const int tc = tid & 15;   // 16 col groups * 8 cols
    const int tr = tid >> 4;   // 8 row groups * 8 rows

    unsigned long long acc[4][8];
#pragma unroll
    for (int i = 0; i < 4; i++)
#pragma unroll
        for (int j = 0; j < 8; j++) acc[i][j] = 0ull;

#pragma unroll 2
    for (int k0 = 0; k0 < Kd; k0 += GTK) {
        // A tile 64x32 -> transposed
#pragma unroll
        for (int i = 0; i < 4; i++) {
            int s = tid + i * 128;
            int m = s >> 3;
            int kq = (s & 7) * 4;
            float4 v = *(const float4*)(A + (size_t)(m0 + m) * Kd + k0 + kq);
            As[kq + 0][m] = v.x;
            As[kq + 1][m] = v.y;
            As[kq + 2][m] = v.z;
            As[kq + 3][m] = v.w;
        }
        // B tile 32x128
#pragma unroll
        for (int i = 0; i < 8; i++) {
            int s = tid + i * 128;
            int k = s >> 5;
            int n4 = (s & 31) * 4;
            *(float4*)&Bs[k][n4] = *(const float4*)(B + (size_t)(k0 + k) * N + n0 + n4);
        }
        __syncthreads();
#pragma unroll
        for (int kk = 0; kk < GTK; kk++) {
            unsigned long long a[4];
#pragma unroll
            for (int i = 0; i < 4; i++)
                a[i] = *(const unsigned long long*)&As[kk][tr * 8 + i * 2];
            float4 b0 = *(const float4*)&Bs[kk][tc * 8];
            float4 b1 = *(const float4*)&Bs[kk][tc * 8 + 4];
            unsigned long long bd[8];
            bd[0] = dup2(b0.x); bd[1] = dup2(b0.y); bd[2] = dup2(b0.z); bd[3] = dup2(b0.w);
            bd[4] = dup2(b1.x); bd[5] = dup2(b1.y); bd[6] = dup2(b1.z); bd[7] = dup2(b1.w);
#pragma unroll
            for (int i = 0; i < 4; i++)
#pragma unroll
                for (int j = 0; j < 8; j++)
                    ffma2(acc[i][j], a[i], bd[j]);
        }
        __syncthreads();
    }

    const int c0 = n0 + tc * 8;

    if (!TOPK) {
#pragma unroll
        for (int i = 0; i < 4; i++) {
            float lo[8], hi[8];
#pragma unroll
            for (int j = 0; j < 8; j++) unpack2(acc[i][j], lo[j], hi[j]);
            if (bias) {
#pragma unroll
                for (int j = 0; j < 8; j++) {
                    float bv = bias[c0 + j];
                    lo[j] += bv; hi[j] += bv;
                }
            }
            int r0 = m0 + tr * 8 + i * 2;
            *(float4*)(C + (size_t)r0 * N + c0)           = make_float4(lo[0], lo[1], lo[2], lo[3]);
            *(float4*)(C + (size_t)r0 * N + c0 + 4)       = make_float4(lo[4], lo[5], lo[6], lo[7]);
            *(float4*)(C + (size_t)(r0 + 1) * N + c0)     = make_float4(hi[0], hi[1], hi[2], hi[3]);
            *(float4*)(C + (size_t)(r0 + 1) * N + c0 + 4) = make_float4(hi[4], hi[5], hi[6], hi[7]);
        }
    } else {
        // bias + per-row softmax partials + top4 over this 128-col tile.
        // Row r is owned by the 16 lanes sharing tr (a half-warp); shfl_xor
        // offsets 1..8 stay inside the half-warp.
        float bv[8];
#pragma unroll
        for (int j = 0; j < 8; j++) bv[j] = bias[c0 + j];

#pragma unroll
        for (int i = 0; i < 4; i++) {
            float lo[8], hi[8];
#pragma unroll
            for (int j = 0; j < 8; j++) {
                unpack2(acc[i][j], lo[j], hi[j]);
                lo[j] += bv[j]; hi[j] += bv[j];
            }
#pragma unroll
            for (int half = 0; half < 2; half++) {
                float* x = half ? hi : lo;
                const int r = tr * 8 + i * 2 + half;
                // row max
                float mx = x[0];
#pragma unroll
                for (int j = 1; j < 8; j++) mx = fmaxf(mx, x[j]);
#pragma unroll
                for (int o = 1; o <= 8; o <<= 1) mx = fmaxf(mx, __shfl_xor_sync(0xffffffffu, mx, o));
                // partial sum of exp
                float s = 0.f;
#pragma unroll
                for (int j = 0; j < 8; j++) s += expf(x[j] - mx);
#pragma unroll
                for (int o = 1; o <= 8; o <<= 1) s += __shfl_xor_sync(0xffffffffu, s, o);
                // local top4 then butterfly merge over 16 lanes
                float v[4] = {-FLT_MAX, -FLT_MAX, -FLT_MAX, -FLT_MAX};
                int   ix[4] = {0x7fffffff, 0x7fffffff, 0x7fffffff, 0x7fffffff};
#pragma unroll
                for (int j = 0; j < 8; j++) ins4(x[j], c0 + j, v, ix);
#pragma unroll
                for (int o = 1; o <= 8; o <<= 1) {
                    float v2[4]; int i2[4];
#pragma unroll
                    for (int p = 0; p < 4; p++) {
                        v2[p] = __shfl_xor_sync(0xffffffffu, v[p], o);
                        i2[p] = __shfl_xor_sync(0xffffffffu, ix[p], o);
                    }
                    merge4(v, ix, v2, i2);
                }
                if (tc == 0) {
                    const int base = (r * NT + bx);
#pragma unroll
                    for (int p = 0; p < 4; p++) {
                        g_pv[base * 4 + p] = v[p];
                        g_pi[base * 4 + p] = ix[p];
                    }
                    g_pm[base] = mx;
                    g_ps[base] = s;
                }
            }
        }
    }
}

// ============ small kernels ============
__global__ void init_last_kernel() {
    g_last[threadIdx.x] = SOS_;
}

// fused: gather e -> q = e@Wq -> attention -> softmax -> ctx -> h = e + ctx
__global__ __launch_bounds__(512) void prep_kernel(
    const float* __restrict__ enc, const int* __restrict__ lens,
    const float* __restrict__ emb, const float* __restrict__ Wq)
{
    const int row = blockIdx.x;
    const int b = row >> 2;
    __shared__ float es[DD];
    __shared__ float qs[DD];
    __shared__ float att[SS];
    __shared__ float red[18];
    const int tid = threadIdx.x, lane = tid & 31, w = tid >> 5;

    const int tok = g_last[row];
    es[tid] = emb[(size_t)tok * DD + tid];
    __syncthreads();

    {
        float qv = 0.f;
#pragma unroll 8
        for (int d = 0; d < DD; d++) qv += es[d] * Wq[(size_t)d * DD + tid];
        qs[tid] = qv;
    }
    __syncthreads();

    const int len = lens[b];
    const float scale = 0.04419417382415922f;

    for (int s = w; s < SS; s += 16) {
        const float* kr = g_encK + ((size_t)b * SS + s) * DD;
        float acc = 0.f;
#pragma unroll 4
        for (int d = lane; d < DD; d += 32) acc += qs[d] * kr[d];
#pragma unroll
        for (int o = 16; o > 0; o >>= 1) acc += __shfl_xor_sync(0xffffffffu, acc, o);
        if (lane == 0) att[s] = (s < len) ? acc * scale : NEG_;
    }
    __syncthreads();

    float x = att[tid];
    float m = x;
#pragma unroll
    for (int o = 16; o > 0; o >>= 1) m = fmaxf(m, __shfl_xor_sync(0xffffffffu, m, o));
    if (lane == 0) red[w] = m;
    __syncthreads();
    if (tid == 0) {
        float mm = red[0];
        for (int i = 1; i < 16; i++) mm = fmaxf(mm, red[i]);
        red[16] = mm;
    }
    __syncthreads();
    m = red[16];
    float p = expf(x - m);
    att[tid] = p;
    float s = p;
#pragma unroll
    for (int o = 16; o > 0; o >>= 1) s += __shfl_xor_sync(0xffffffffu, s, o);
    if (lane == 0) red[w] = s;
    __syncthreads();
    if (tid == 0) {
        float ss = 0.f;
        for (int i = 0; i < 16; i++) ss += red[i];
        red[17] = 1.0f / ss;
    }
    __syncthreads();
    const float inv = red[17];

    const float* er = enc + (size_t)b * SS * DD;
    float c = 0.f;
#pragma unroll 4
    for (int ss2 = 0; ss2 < SS; ss2++) c += att[ss2] * er[(size_t)ss2 * DD + tid];
    g_h[row * DD + tid] = es[tid] + c * inv;
}

// ============ reduce partials + beam combine (one block per batch) ============
__global__ __launch_bounds__(512) void redcomb_kernel(int t, int srcbuf) {
    const int b = blockIdx.x;
    const int tid = threadIdx.x;
    const int rloc = tid >> 7;      // 0..3
    const int t2 = tid & 127;       // 0..127
    const int row = b * KK + rloc;

    float v[4] = {-FLT_MAX, -FLT_MAX, -FLT_MAX, -FLT_MAX};
    int   ix[4] = {0x7fffffff, 0x7fffffff, 0x7fffffff, 0x7fffffff};
    float M = -FLT_MAX, S = 0.f;

    for (int p = t2; p < NT; p += 128) {
        const int base = row * NT + p;
#pragma unroll
        for (int q = 0; q < 4; q++) ins4(g_pv[base * 4 + q], g_pi[base * 4 + q], v, ix);
        float pm = g_pm[base], ps = g_ps[base];
        if (pm > M) { S = S * expf(M - pm) + ps; M = pm; }
        else        { S += ps * expf(pm - M); }
    }

    __shared__ float sv[512 * 4];
    __shared__ int   si[512 * 4];
    __shared__ float sM[512], sS[512];
#pragma unroll
    for (int p = 0; p < 4; p++) { sv[tid * 4 + p] = v[p]; si[tid * 4 + p] = ix[p]; }
    sM[tid] = M; sS[tid] = S;
    __syncthreads();

    for (int off = 64; off > 0; off >>= 1) {
        if (t2 < off) {
            const int o = tid + off;
            float v2[4]; int i2[4];
#pragma unroll
            for (int p = 0; p < 4; p++) { v2[p] = sv[o * 4 + p]; i2[p] = si[o * 4 + p]; }
            float va[4]; int ia[4];
#pragma unroll
            for (int p = 0; p < 4; p++) { va[p] = sv[tid * 4 + p]; ia[p] = si[tid * 4 + p]; }
            merge4(va, ia, v2, i2);
#pragma unroll
            for (int p = 0; p < 4; p++) { sv[tid * 4 + p] = va[p]; si[tid * 4 + p] = ia[p]; }
            float M2 = sM[o], S2 = sS[o];
            float M1 = sM[tid], S1 = sS[tid];
            if (M2 > M1) { S1 = S1 * expf(M1 - M2) + S2; M1 = M2; }
            else         { S1 += S2 * expf(M2 - M1); }
            sM[tid] = M1; sS[tid] = S1;
        }
        __syncthreads();
    }

    __shared__ float rowv[KK][4];
    __shared__ int   rowi[KK][4];
    __shared__ float rowlse[KK];
    if (t2 == 0) {
#pragma unroll
        for (int p = 0; p < 4; p++) { rowv[rloc][p] = sv[tid * 4 + p]; rowi[rloc][p] = si[tid * 4 + p]; }
        rowlse[rloc] = sM[tid] + logf(sS[tid]);
    }
    __syncthreads();

    if (t == 1) {
        // expand SOS (all rows identical; use row k=0)
        __shared__ int toks[4];
        __shared__ float scs[4];
        if (tid == 0) {
            float lse = rowlse[0];
            for (int k = 0; k < 4; k++) {
                scs[k] = rowv[0][k] - lse;
                toks[k] = rowi[0][k];
            }
        }
        __syncthreads();
        if (tid < TT) {
            for (int k = 0; k < 4; k++) {
                int val = (tid == 0) ? SOS_ : ((tid == 1) ? toks[k] : PAD_);
                g_seqs[0][(b * KK + k) * TT + tid] = val;
            }
        }
        if (tid < 4) {
            g_scores[b * KK + tid] = scs[tid];
            g_finished[b * KK + tid] = (toks[tid] == EOS_) ? 1 : 0;
            g_last[b * KK + tid] = toks[tid];
        }
    } else {
        __shared__ float total[16];
        __shared__ int   candv[16];
        __shared__ int nbeam[4], ntok[4], nfin[4];
        __shared__ float nsc[4];
        if (tid == 0) {
            for (int k = 0; k < 4; k++) {
                int r = b * KK + k;
                bool fin = (g_finished[r] != 0);
                float lse = rowlse[k];
                float sc = g_scores[r];
                for (int j = 0; j < 4; j++) {
                    float lp; int vtok;
                    if (fin) { lp = (j == 0) ? 0.f : NEG_; vtok = PAD_; }
                    else { lp = rowv[k][j] - lse; vtok = rowi[k][j]; }
                    total[k * 4 + j] = sc + lp;
                    candv[k * 4 + j] = vtok;
                }
            }
            bool used[16];
            for (int i = 0; i < 16; i++) used[i] = false;
            for (int p = 0; p < 4; p++) {
                int biq = -1; float bvq = -FLT_MAX;
                for (int i = 0; i < 16; i++) {
                    if (!used[i] && total[i] > bvq) { bvq = total[i]; biq = i; }
                }
                used[biq] = true;
                nbeam[p] = biq >> 2;
                ntok[p] = candv[biq];
                nsc[p] = bvq;
            }
            for (int p = 0; p < 4; p++)
                nfin[p] = (g_finished[b * KK + nbeam[p]] != 0 || ntok[p] == EOS_) ? 1 : 0;
        }
        __syncthreads();
        const int* src = g_seqs[srcbuf];
        int* dst = g_seqs[srcbuf ^ 1];
        if (tid < KK * TT) {
            int k = tid >> 6, pos = tid & 63;
            int x = src[(b * KK + nbeam[k]) * TT + pos];
            dst[(b * KK + k) * TT + pos] = (pos == t) ? ntok[k] : x;
        }
        __syncthreads();
        if (tid < 4) {
            g_scores[b * KK + tid] = nsc[tid];
            g_finished[b * KK + tid] = nfin[tid];
            g_last[b * KK + tid] = ntok[tid];
        }
    }
}

// ---- final: argmax beam per batch ----
__global__ void finalize_kernel(float* out, int out_size, int srcbuf) {
    const int b = blockIdx.x, tid = threadIdx.x;  // 64 threads
    __shared__ int bbk;
    __shared__ float bbs;
    if (tid == 0) {
        int bi = 0; float bv = g_scores[b * KK];
        for (int k = 1; k < 4; k++) {
            if (g_scores[b * KK + k] > bv) { bv = g_scores[b * KK + k]; bi = k; }
        }
        bbk = bi; bbs = bv;
    }
    __syncthreads();
    if (out_size == BB) {
        if (tid == 0) out[b] = bbs;
        return;
    }
    int idx = b * TT + tid;
    if (idx < out_size)
        out[idx] = (float)g_seqs[srcbuf][(b * KK + bbk) * TT + tid];
    if (tid == 0 && BB * TT + b < out_size)
        out[BB * TT + b] = bbs;
}

// ============ host launcher ============
extern "C" void kernel_launch(void* const* d_in, const int* in_sizes, int n_in,
                              void* d_out, int out_size)
{
    const float* enc = (const float*)d_in[0];
    const int*   lens = (const int*)d_in[1];
    const float* emb = (const float*)d_in[2];
    const float* Wq  = (const float*)d_in[3];
    const float* Wk  = (const float*)d_in[4];
    const float* Wfc = (const float*)d_in[5];
    const float* bfc = (const float*)d_in[6];

    float *p_encK, *p_h;
    cudaGetSymbolAddress((void**)&p_encK, g_encK);
    cudaGetSymbolAddress((void**)&p_h, g_h);

    // encK = enc @ W_k   (8192 x 512 x 512)
    {
        dim3 grid(DD / 128, (BB * SS) / 64);
        gemm2_kernel<false><<<grid, 128>>>(enc, Wk, nullptr, p_encK, BB * SS, DD, DD);
    }

    init_last_kernel<<<1, RR>>>();

    // step 1
    prep_kernel<<<RR, 512>>>(enc, lens, emb, Wq);
    gemm2_kernel<true><<<dim3(NT, 1), 128>>>(p_h, Wfc, bfc, nullptr, RR, VV, DD);
    redcomb_kernel<<<BB, 512>>>(1, 0);

    // steps 2..63
    for (int t = 2; t < TT; t++) {
        prep_kernel<<<RR, 512>>>(enc, lens, emb, Wq);
        gemm2_kernel<true><<<dim3(NT, 1), 128>>>(p_h, Wfc, bfc, nullptr, RR, VV, DD);
        redcomb_kernel<<<BB, 512>>>(t, t & 1);
    }

    finalize_kernel<<<BB, TT>>>((float*)d_out, out_size, 0);
}

// round 5
// speedup vs baseline: 1.3420x; 1.3420x over previous
#include <cuda_runtime.h>
#include <math.h>
#include <float.h>

// Problem constants
#define BB   16      // batch
#define KK   4       // beam
#define RR   64      // BB*KK rows
#define SS   512     // encoder seq
#define DD   512     // model dim
#define VV   32000   // vocab
#define TT   64      // max len
#define SOS_ 1
#define EOS_ 2
#define PAD_ 0
#define NEG_ (-1e9f)

#define NT   (VV / 64)   // 500 N-tiles for logits GEMM

// -------- device state --------
__device__ float g_encK[BB * SS * DD];      // 16.8 MB
__device__ float g_h[RR * DD];
__device__ int   g_seqs[2][RR * TT];
__device__ float g_scores2[2][RR];
__device__ int   g_fin2[2][RR];
// per-(row, n-tile) partials from the logits GEMM epilogue
__device__ float g_pv[RR * NT * 4];
__device__ int   g_pi[RR * NT * 4];
__device__ float g_pm[RR * NT];
__device__ float g_ps[RR * NT];

// ---------------- packed f32x2 helpers ----------------
__device__ __forceinline__ void ffma2(unsigned long long& d,
                                      unsigned long long a,
                                      unsigned long long b) {
    asm("fma.rn.f32x2 %0, %1, %2, %0;" : "+l"(d) : "l"(a), "l"(b));
}
__device__ __forceinline__ unsigned long long dup2(float x) {
    unsigned long long r;
    asm("mov.b64 %0, {%1, %1};" : "=l"(r) : "f"(x));
    return r;
}
__device__ __forceinline__ void unpack2(unsigned long long v, float& lo, float& hi) {
    asm("mov.b64 {%0, %1}, %2;" : "=f"(lo), "=f"(hi) : "l"(v));
}

__device__ __forceinline__ bool better_vi(float v1, int i1, float v2, int i2) {
    return (v1 > v2) || (v1 == v2 && i1 < i2);
}
__device__ __forceinline__ void ins4(float x, int c, float* v, int* ix) {
    if (better_vi(x, c, v[3], ix[3])) {
        v[3] = x; ix[3] = c;
#pragma unroll
        for (int p = 3; p > 0; p--) {
            if (better_vi(v[p], ix[p], v[p - 1], ix[p - 1])) {
                float tv = v[p]; v[p] = v[p - 1]; v[p - 1] = tv;
                int ti = ix[p]; ix[p] = ix[p - 1]; ix[p - 1] = ti;
            }
        }
    }
}
__device__ __forceinline__ void merge4(float* v, int* ix, const float* v2, const int* i2) {
    float ov[4]; int oi[4];
    int pa = 0, pb = 0;
#pragma unroll
    for (int t = 0; t < 4; t++) {
        bool takeA = (pb >= 4) || (pa < 4 && better_vi(v[pa], ix[pa], v2[pb], i2[pb]));
        if (takeA) { ov[t] = v[pa]; oi[t] = ix[pa]; pa++; }
        else       { ov[t] = v2[pb]; oi[t] = i2[pb]; pb++; }
    }
#pragma unroll
    for (int p = 0; p < 4; p++) { v[p] = ov[p]; ix[p] = oi[p]; }
}

// ============ FFMA2 GEMM, tile 64x64, 128 threads (R3 mainloop) ============
// TOPK=false: writes C (+bias). TOPK=true: per-row top4/max/sumexp partials via smem staging.
#define GTK 32

template<bool TOPK>
__global__ __launch_bounds__(128) void gemm2_kernel(
    const float* __restrict__ A, const float* __restrict__ B,
    const float* __restrict__ bias, float* __restrict__ C,
    int M, int N, int Kd)
{
    // union: mainloop As[32][66] + Bs[32][64]  <->  epilogue Cs[64][65]
    __shared__ __align__(16) float smemU[32 * 66 + 32 * 64];  // 4160 floats
    float (*As)[66] = (float (*)[66])smemU;
    float (*Bs)[64] = (float (*)[64])(smemU + 32 * 66);
    float (*Cs)[65] = (float (*)[65])smemU;

    const int tid = threadIdx.x;
    const int bx = blockIdx.x;
    const int n0 = bx * 64;
    const int m0 = blockIdx.y * 64;
    const int tc = tid & 15;   // 16 col groups * 4 cols
    const int tr = tid >> 4;   // 8 row groups * 8 rows

    unsigned long long acc[4][4];
#pragma unroll
    for (int i = 0; i < 4; i++)
#pragma unroll
        for (int j = 0; j < 4; j++) acc[i][j] = 0ull;

#pragma unroll 2
    for (int k0 = 0; k0 < Kd; k0 += GTK) {
#pragma unroll
        for (int i = 0; i < 4; i++) {
            int s = tid + i * 128;
            int m = s >> 3;
            int kq = (s & 7) * 4;
            float4 v = *(const float4*)(A + (size_t)(m0 + m) * Kd + k0 + kq);
            As[kq + 0][m] = v.x;
            As[kq + 1][m] = v.y;
            As[kq + 2][m] = v.z;
            As[kq + 3][m] = v.w;
        }
#pragma unroll
        for (int i = 0; i < 4; i++) {
            int s = tid + i * 128;
            int k = s >> 4;
            int n4 = (s & 15) * 4;
            *(float4*)&Bs[k][n4] = *(const float4*)(B + (size_t)(k0 + k) * N + n0 + n4);
        }
        __syncthreads();
#pragma unroll
        for (int kk = 0; kk < GTK; kk++) {
            unsigned long long a[4];
#pragma unroll
            for (int i = 0; i < 4; i++)
                a[i] = *(const unsigned long long*)&As[kk][tr * 8 + i * 2];
            float4 bq = *(const float4*)&Bs[kk][tc * 4];
            unsigned long long bd[4];
            bd[0] = dup2(bq.x); bd[1] = dup2(bq.y);
            bd[2] = dup2(bq.z); bd[3] = dup2(bq.w);
#pragma unroll
            for (int i = 0; i < 4; i++)
#pragma unroll
                for (int j = 0; j < 4; j++)
                    ffma2(acc[i][j], a[i], bd[j]);
        }
        __syncthreads();
    }

    const int c0 = n0 + tc * 4;

    if (!TOPK) {
#pragma unroll
        for (int i = 0; i < 4; i++) {
            float lo[4], hi[4];
#pragma unroll
            for (int j = 0; j < 4; j++) unpack2(acc[i][j], lo[j], hi[j]);
            int r0 = m0 + tr * 8 + i * 2;
            if (bias) {
#pragma unroll
                for (int j = 0; j < 4; j++) {
                    float bv = bias[c0 + j];
                    lo[j] += bv; hi[j] += bv;
                }
            }
            *(float4*)(C + (size_t)r0 * N + c0)       = make_float4(lo[0], lo[1], lo[2], lo[3]);
            *(float4*)(C + (size_t)(r0 + 1) * N + c0) = make_float4(hi[0], hi[1], hi[2], hi[3]);
        }
    } else {
        // stage C tile (+bias) into smem; accumulators die here
#pragma unroll
        for (int i = 0; i < 4; i++) {
            float lo[4], hi[4];
#pragma unroll
            for (int j = 0; j < 4; j++) unpack2(acc[i][j], lo[j], hi[j]);
            int r0 = tr * 8 + i * 2;
            int cc = tc * 4;
#pragma unroll
            for (int j = 0; j < 4; j++) {
                float bv = bias[c0 + j];
                Cs[r0][cc + j]     = lo[j] + bv;
                Cs[r0 + 1][cc + j] = hi[j] + bv;
            }
        }
        __syncthreads();

        // 2 threads per row, 32 cols each
        const int row = tid >> 1;
        const int half = tid & 1;
        const int cbase = half * 32;
        float v[4] = {-FLT_MAX, -FLT_MAX, -FLT_MAX, -FLT_MAX};
        int   ix[4] = {0x7fffffff, 0x7fffffff, 0x7fffffff, 0x7fffffff};
#pragma unroll 8
        for (int c = 0; c < 32; c++)
            ins4(Cs[row][cbase + c], n0 + cbase + c, v, ix);
        // v[0] is this half-row's max; exchange with partner (tid^1, same warp)
        float M1 = fmaxf(v[0], __shfl_xor_sync(0xffffffffu, v[0], 1));
        float s = 0.f;
#pragma unroll 8
        for (int c = 0; c < 32; c++)
            s += expf(Cs[row][cbase + c] - M1);
        s += __shfl_xor_sync(0xffffffffu, s, 1);
        float v2[4]; int i2[4];
#pragma unroll
        for (int p = 0; p < 4; p++) {
            v2[p] = __shfl_xor_sync(0xffffffffu, v[p], 1);
            i2[p] = __shfl_xor_sync(0xffffffffu, ix[p], 1);
        }
        merge4(v, ix, v2, i2);
        if (half == 0) {
            const int base = row * NT + bx;
#pragma unroll
            for (int p = 0; p < 4; p++) {
                g_pv[base * 4 + p] = v[p];
                g_pi[base * 4 + p] = ix[p];
            }
            g_pm[base] = M1;
            g_ps[base] = s;
        }
    }
}

// ============ fused combine + prep ============
// t==1: token=SOS, no combine.  t in [2,64]: reduce partials + beam combine
// (writes position t-1; t==2 is the SOS expansion).  doAttn=0 skips attention (t==64).
__global__ __launch_bounds__(512) void prep_kernel(
    int t, int doAttn,
    const float* __restrict__ enc, const int* __restrict__ lens,
    const float* __restrict__ emb, const float* __restrict__ Wq)
{
    const int row = blockIdx.x;
    const int b = row >> 2;
    const int myk = row & 3;
    const int tid = threadIdx.x, lane = tid & 31, w = tid >> 5;

    __shared__ float sv[512 * 4];
    __shared__ int   si[512 * 4];
    __shared__ float sM[512], sS[512];
    __shared__ float rowv[KK][4];
    __shared__ int   rowi[KK][4];
    __shared__ float rowlse[KK];
    __shared__ int   s_ntok[4];

    if (t >= 2) {
        const int rloc = tid >> 7;      // 0..3 -> beam row of this batch
        const int t2 = tid & 127;
        const int prow = b * KK + rloc;

        float v[4] = {-FLT_MAX, -FLT_MAX, -FLT_MAX, -FLT_MAX};
        int   ix[4] = {0x7fffffff, 0x7fffffff, 0x7fffffff, 0x7fffffff};
        float M = -FLT_MAX, S = 0.f;
        for (int p = t2; p < NT; p += 128) {
            const int base = prow * NT + p;
#pragma unroll
            for (int q = 0; q < 4; q++) ins4(g_pv[base * 4 + q], g_pi[base * 4 + q], v, ix);
            float pm = g_pm[base], ps = g_ps[base];
            if (pm > M) { S = S * expf(M - pm) + ps; M = pm; }
            else        { S += ps * expf(pm - M); }
        }
#pragma unroll
        for (int p = 0; p < 4; p++) { sv[tid * 4 + p] = v[p]; si[tid * 4 + p] = ix[p]; }
        sM[tid] = M; sS[tid] = S;
        __syncthreads();

        for (int off = 64; off > 0; off >>= 1) {
            if (t2 < off) {
                const int o = tid + off;
                float v2[4]; int i2[4];
#pragma unroll
                for (int p = 0; p < 4; p++) { v2[p] = sv[o * 4 + p]; i2[p] = si[o * 4 + p]; }
                float va[4]; int ia[4];
#pragma unroll
                for (int p = 0; p < 4; p++) { va[p] = sv[tid * 4 + p]; ia[p] = si[tid * 4 + p]; }
                merge4(va, ia, v2, i2);
#pragma unroll
                for (int p = 0; p < 4; p++) { sv[tid * 4 + p] = va[p]; si[tid * 4 + p] = ia[p]; }
                float M2 = sM[o], S2 = sS[o];
                float Ma = sM[tid], Sa = sS[tid];
                if (M2 > Ma) { Sa = Sa * expf(Ma - M2) + S2; Ma = M2; }
                else         { Sa += S2 * expf(M2 - Ma); }
                sM[tid] = Ma; sS[tid] = Sa;
            }
            __syncthreads();
        }
        if (t2 == 0) {
#pragma unroll
            for (int p = 0; p < 4; p++) { rowv[rloc][p] = sv[tid * 4 + p]; rowi[rloc][p] = si[tid * 4 + p]; }
            rowlse[rloc] = sM[tid] + logf(sS[tid]);
        }
        __syncthreads();

        const int rp = (t - 1) & 1;  // read parity
        const int wp = t & 1;        // write parity
        const int pos = t - 1;       // sequence position being written

        if (t == 2) {
            // SOS expansion (all rows identical; use rloc 0)
            if (tid == 0) {
#pragma unroll
                for (int k = 0; k < 4; k++) s_ntok[k] = rowi[0][k];
            }
            __syncthreads();
            if (myk == 0) {
                if (tid < TT) {
                    for (int k = 0; k < 4; k++) {
                        int val = (tid == 0) ? SOS_ : ((tid == 1) ? s_ntok[k] : PAD_);
                        g_seqs[wp][(b * KK + k) * TT + tid] = val;
                    }
                }
                if (tid < 4) {
                    g_scores2[wp][b * KK + tid] = rowv[0][tid] - rowlse[0];
                    g_fin2[wp][b * KK + tid] = (s_ntok[tid] == EOS_) ? 1 : 0;
                }
            }
            __syncthreads();
        } else {
            __shared__ int nbeam[4], nfin[4];
            __shared__ float nsc[4];
            if (tid == 0) {
                float total[16]; int candv[16];
                for (int k = 0; k < 4; k++) {
                    int r = b * KK + k;
                    bool fin = (g_fin2[rp][r] != 0);
                    float lse = rowlse[k];
                    float sc = g_scores2[rp][r];
                    for (int j = 0; j < 4; j++) {
                        float lp; int vtok;
                        if (fin) { lp = (j == 0) ? 0.f : NEG_; vtok = PAD_; }
                        else { lp = rowv[k][j] - lse; vtok = rowi[k][j]; }
                        total[k * 4 + j] = sc + lp;
                        candv[k * 4 + j] = vtok;
                    }
                }
                bool used[16];
                for (int i = 0; i < 16; i++) used[i] = false;
                for (int p = 0; p < 4; p++) {
                    int biq = -1; float bvq = -FLT_MAX;
                    for (int i = 0; i < 16; i++)
                        if (!used[i] && total[i] > bvq) { bvq = total[i]; biq = i; }
                    used[biq] = true;
                    nbeam[p] = biq >> 2;
                    s_ntok[p] = candv[biq];
                    nsc[p] = bvq;
                }
                for (int p = 0; p < 4; p++)
                    nfin[p] = (g_fin2[rp][b * KK + nbeam[p]] != 0 || s_ntok[p] == EOS_) ? 1 : 0;
            }
            __syncthreads();
            if (myk == 0) {
                if (tid < KK * TT) {
                    int k = tid >> 6, ps2 = tid & 63;
                    int x = g_seqs[rp][(b * KK + nbeam[k]) * TT + ps2];
                    g_seqs[wp][(b * KK + k) * TT + ps2] = (ps2 == pos) ? s_ntok[k] : x;
                }
                if (tid < 4) {
                    g_scores2[wp][b * KK + tid] = nsc[tid];
                    g_fin2[wp][b * KK + tid] = nfin[tid];
                }
            }
            __syncthreads();
        }
    }

    if (!doAttn) return;

    const int tok = (t == 1) ? SOS_ : s_ntok[myk];

    __shared__ float es[DD];
    __shared__ float qs[DD];
    __shared__ float att[SS];
    __shared__ float red[18];

    es[tid] = emb[(size_t)tok * DD + tid];
    __syncthreads();

    {
        float qv = 0.f;
#pragma unroll 8
        for (int d = 0; d < DD; d++) qv += es[d] * Wq[(size_t)d * DD + tid];
        qs[tid] = qv;
    }
    __syncthreads();

    const int len = lens[b];
    const float scale = 0.04419417382415922f;

    for (int s = w; s < SS; s += 16) {
        const float* kr = g_encK + ((size_t)b * SS + s) * DD;
        float acc = 0.f;
#pragma unroll 4
        for (int d = lane; d < DD; d += 32) acc += qs[d] * kr[d];
#pragma unroll
        for (int o = 16; o > 0; o >>= 1) acc += __shfl_xor_sync(0xffffffffu, acc, o);
        if (lane == 0) att[s] = (s < len) ? acc * scale : NEG_;
    }
    __syncthreads();

    float x = att[tid];
    float m = x;
#pragma unroll
    for (int o = 16; o > 0; o >>= 1) m = fmaxf(m, __shfl_xor_sync(0xffffffffu, m, o));
    if (lane == 0) red[w] = m;
    __syncthreads();
    if (tid == 0) {
        float mm = red[0];
        for (int i = 1; i < 16; i++) mm = fmaxf(mm, red[i]);
        red[16] = mm;
    }
    __syncthreads();
    m = red[16];
    float p = expf(x - m);
    att[tid] = p;
    float s = p;
#pragma unroll
    for (int o = 16; o > 0; o >>= 1) s += __shfl_xor_sync(0xffffffffu, s, o);
    if (lane == 0) red[w] = s;
    __syncthreads();
    if (tid == 0) {
        float ss = 0.f;
        for (int i = 0; i < 16; i++) ss += red[i];
        red[17] = 1.0f / ss;
    }
    __syncthreads();
    const float inv = red[17];

    const float* er = enc + (size_t)b * SS * DD;
    float c = 0.f;
#pragma unroll 4
    for (int ss2 = 0; ss2 < SS; ss2++) c += att[ss2] * er[(size_t)ss2 * DD + tid];
    g_h[row * DD + tid] = es[tid] + c * inv;
}

// ---- final: argmax beam per batch ----
__global__ void finalize_kernel(float* out, int out_size, int srcbuf) {
    const int b = blockIdx.x, tid = threadIdx.x;  // 64 threads
    __shared__ int bbk;
    __shared__ float bbs;
    if (tid == 0) {
        int bi = 0; float bv = g_scores2[srcbuf][b * KK];
        for (int k = 1; k < 4; k++) {
            if (g_scores2[srcbuf][b * KK + k] > bv) { bv = g_scores2[srcbuf][b * KK + k]; bi = k; }
        }
        bbk = bi; bbs = bv;
    }
    __syncthreads();
    if (out_size == BB) {
        if (tid == 0) out[b] = bbs;
        return;
    }
    int idx = b * TT + tid;
    if (idx < out_size)
        out[idx] = (float)g_seqs[srcbuf][(b * KK + bbk) * TT + tid];
    if (tid == 0 && BB * TT + b < out_size)
        out[BB * TT + b] = bbs;
}

// ============ host launcher ============
extern "C" void kernel_launch(void* const* d_in, const int* in_sizes, int n_in,
                              void* d_out, int out_size)
{
    const float* enc = (const float*)d_in[0];
    const int*   lens = (const int*)d_in[1];
    const float* emb = (const float*)d_in[2];
    const float* Wq  = (const float*)d_in[3];
    const float* Wk  = (const float*)d_in[4];
    const float* Wfc = (const float*)d_in[5];
    const float* bfc = (const float*)d_in[6];

    float *p_encK, *p_h;
    cudaGetSymbolAddress((void**)&p_encK, g_encK);
    cudaGetSymbolAddress((void**)&p_h, g_h);

    // encK = enc @ W_k   (8192 x 512 x 512)
    {
        dim3 grid(DD / 64, (BB * SS) / 64);
        gemm2_kernel<false><<<grid, 128>>>(enc, Wk, nullptr, p_encK, BB * SS, DD, DD);
    }

    // t=1: SOS prep + logits
    prep_kernel<<<RR, 512>>>(1, 1, enc, lens, emb, Wq);
    gemm2_kernel<true><<<dim3(NT, 1), 128>>>(p_h, Wfc, bfc, nullptr, RR, VV, DD);

    // t=2..63: combine (writes pos t-1) + attention, then logits
    for (int t = 2; t < TT; t++) {
        prep_kernel<<<RR, 512>>>(t, 1, enc, lens, emb, Wq);
        gemm2_kernel<true><<<dim3(NT, 1), 128>>>(p_h, Wfc, bfc, nullptr, RR, VV, DD);
    }

    // t=64: final combine only (writes pos 63, parity 0)
    prep_kernel<<<RR, 512>>>(TT, 0, enc, lens, emb, Wq);

    finalize_kernel<<<BB, TT>>>((float*)d_out, out_size, 0);
}

// round 6
// speedup vs baseline: 1.7496x; 1.3037x over previous
#include <cuda_runtime.h>
#include <math.h>
#include <float.h>

// Problem constants
#define BB   16      // batch
#define KK   4       // beam
#define RR   64      // BB*KK rows
#define SS   512     // encoder seq
#define DD   512     // model dim
#define VV   32000   // vocab
#define TT   64      // max len
#define SOS_ 1
#define EOS_ 2
#define PAD_ 0
#define NEG_ (-1e9f)

#define NT   (VV / 64)   // 500 N-tiles for logits GEMM

// -------- device state --------
__device__ float g_encK[BB * SS * DD];      // 16.8 MB
__device__ float g_P[BB * SS * DD];         // 16.8 MB: P = encK @ Wq^T
__device__ float g_WqT[DD * DD];
__device__ float g_e[RR * DD];
__device__ float g_h[RR * DD];
__device__ float g_attp[RR * SS];           // unnormalized exp scores
__device__ float g_am[RR * 4];              // per-quarter max
__device__ float g_as[RR * 4];              // per-quarter sumexp
__device__ int   g_seqs[2][RR * TT];
__device__ float g_scores2[2][RR];
__device__ int   g_fin2[2][RR];
// per-(row, n-tile) partials from the logits GEMM epilogue
__device__ float g_pv[RR * NT * 4];
__device__ int   g_pi[RR * NT * 4];
__device__ float g_pm[RR * NT];
__device__ float g_ps[RR * NT];

// ---------------- packed f32x2 helpers ----------------
__device__ __forceinline__ void ffma2(unsigned long long& d,
                                      unsigned long long a,
                                      unsigned long long b) {
    asm("fma.rn.f32x2 %0, %1, %2, %0;" : "+l"(d) : "l"(a), "l"(b));
}
__device__ __forceinline__ unsigned long long dup2(float x) {
    unsigned long long r;
    asm("mov.b64 %0, {%1, %1};" : "=l"(r) : "f"(x));
    return r;
}
__device__ __forceinline__ void unpack2(unsigned long long v, float& lo, float& hi) {
    asm("mov.b64 {%0, %1}, %2;" : "=f"(lo), "=f"(hi) : "l"(v));
}

__device__ __forceinline__ bool better_vi(float v1, int i1, float v2, int i2) {
    return (v1 > v2) || (v1 == v2 && i1 < i2);
}
__device__ __forceinline__ void ins4(float x, int c, float* v, int* ix) {
    if (better_vi(x, c, v[3], ix[3])) {
        v[3] = x; ix[3] = c;
#pragma unroll
        for (int p = 3; p > 0; p--) {
            if (better_vi(v[p], ix[p], v[p - 1], ix[p - 1])) {
                float tv = v[p]; v[p] = v[p - 1]; v[p - 1] = tv;
                int ti = ix[p]; ix[p] = ix[p - 1]; ix[p - 1] = ti;
            }
        }
    }
}
__device__ __forceinline__ void merge4(float* v, int* ix, const float* v2, const int* i2) {
    float ov[4]; int oi[4];
    int pa = 0, pb = 0;
#pragma unroll
    for (int t = 0; t < 4; t++) {
        bool takeA = (pb >= 4) || (pa < 4 && better_vi(v[pa], ix[pa], v2[pb], i2[pb]));
        if (takeA) { ov[t] = v[pa]; oi[t] = ix[pa]; pa++; }
        else       { ov[t] = v2[pb]; oi[t] = i2[pb]; pb++; }
    }
#pragma unroll
    for (int p = 0; p < 4; p++) { v[p] = ov[p]; ix[p] = oi[p]; }
}

// ============ FFMA2 GEMM, tile 64x64, 128 threads ============
#define GTK 32

template<bool TOPK>
__global__ __launch_bounds__(128) void gemm2_kernel(
    const float* __restrict__ A, const float* __restrict__ B,
    const float* __restrict__ bias, float* __restrict__ C,
    int M, int N, int Kd)
{
    __shared__ __align__(16) float smemU[32 * 66 + 32 * 64];
    float (*As)[66] = (float (*)[66])smemU;
    float (*Bs)[64] = (float (*)[64])(smemU + 32 * 66);
    float (*Cs)[65] = (float (*)[65])smemU;

    const int tid = threadIdx.x;
    const int bx = blockIdx.x;
    const int n0 = bx * 64;
    const int m0 = blockIdx.y * 64;
    const int tc = tid & 15;
    const int tr = tid >> 4;

    unsigned long long acc[4][4];
#pragma unroll
    for (int i = 0; i < 4; i++)
#pragma unroll
        for (int j = 0; j < 4; j++) acc[i][j] = 0ull;

#pragma unroll 2
    for (int k0 = 0; k0 < Kd; k0 += GTK) {
#pragma unroll
        for (int i = 0; i < 4; i++) {
            int s = tid + i * 128;
            int m = s >> 3;
            int kq = (s & 7) * 4;
            float4 v = *(const float4*)(A + (size_t)(m0 + m) * Kd + k0 + kq);
            As[kq + 0][m] = v.x;
            As[kq + 1][m] = v.y;
            As[kq + 2][m] = v.z;
            As[kq + 3][m] = v.w;
        }
#pragma unroll
        for (int i = 0; i < 4; i++) {
            int s = tid + i * 128;
            int k = s >> 4;
            int n4 = (s & 15) * 4;
            *(float4*)&Bs[k][n4] = *(const float4*)(B + (size_t)(k0 + k) * N + n0 + n4);
        }
        __syncthreads();
#pragma unroll
        for (int kk = 0; kk < GTK; kk++) {
            unsigned long long a[4];
#pragma unroll
            for (int i = 0; i < 4; i++)
                a[i] = *(const unsigned long long*)&As[kk][tr * 8 + i * 2];
            float4 bq = *(const float4*)&Bs[kk][tc * 4];
            unsigned long long bd[4];
            bd[0] = dup2(bq.x); bd[1] = dup2(bq.y);
            bd[2] = dup2(bq.z); bd[3] = dup2(bq.w);
#pragma unroll
            for (int i = 0; i < 4; i++)
#pragma unroll
                for (int j = 0; j < 4; j++)
                    ffma2(acc[i][j], a[i], bd[j]);
        }
        __syncthreads();
    }

    const int c0 = n0 + tc * 4;

    if (!TOPK) {
#pragma unroll
        for (int i = 0; i < 4; i++) {
            float lo[4], hi[4];
#pragma unroll
            for (int j = 0; j < 4; j++) unpack2(acc[i][j], lo[j], hi[j]);
            int r0 = m0 + tr * 8 + i * 2;
            if (bias) {
#pragma unroll
                for (int j = 0; j < 4; j++) {
                    float bv = bias[c0 + j];
                    lo[j] += bv; hi[j] += bv;
                }
            }
            *(float4*)(C + (size_t)r0 * N + c0)       = make_float4(lo[0], lo[1], lo[2], lo[3]);
            *(float4*)(C + (size_t)(r0 + 1) * N + c0) = make_float4(hi[0], hi[1], hi[2], hi[3]);
        }
    } else {
#pragma unroll
        for (int i = 0; i < 4; i++) {
            float lo[4], hi[4];
#pragma unroll
            for (int j = 0; j < 4; j++) unpack2(acc[i][j], lo[j], hi[j]);
            int r0 = tr * 8 + i * 2;
            int cc = tc * 4;
#pragma unroll
            for (int j = 0; j < 4; j++) {
                float bv = bias[c0 + j];
                Cs[r0][cc + j]     = lo[j] + bv;
                Cs[r0 + 1][cc + j] = hi[j] + bv;
            }
        }
        __syncthreads();

        const int row = tid >> 1;
        const int half = tid & 1;
        const int cbase = half * 32;
        float v[4] = {-FLT_MAX, -FLT_MAX, -FLT_MAX, -FLT_MAX};
        int   ix[4] = {0x7fffffff, 0x7fffffff, 0x7fffffff, 0x7fffffff};
#pragma unroll 8
        for (int c = 0; c < 32; c++)
            ins4(Cs[row][cbase + c], n0 + cbase + c, v, ix);
        float M1 = fmaxf(v[0], __shfl_xor_sync(0xffffffffu, v[0], 1));
        float s = 0.f;
#pragma unroll 8
        for (int c = 0; c < 32; c++)
            s += expf(Cs[row][cbase + c] - M1);
        s += __shfl_xor_sync(0xffffffffu, s, 1);
        float v2[4]; int i2[4];
#pragma unroll
        for (int p = 0; p < 4; p++) {
            v2[p] = __shfl_xor_sync(0xffffffffu, v[p], 1);
            i2[p] = __shfl_xor_sync(0xffffffffu, ix[p], 1);
        }
        merge4(v, ix, v2, i2);
        if (half == 0) {
            const int base = row * NT + bx;
#pragma unroll
            for (int p = 0; p < 4; p++) {
                g_pv[base * 4 + p] = v[p];
                g_pi[base * 4 + p] = ix[p];
            }
            g_pm[base] = M1;
            g_ps[base] = s;
        }
    }
}

// ============ Wq transpose (32x32 tiles) ============
__global__ void transpose_kernel(const float* __restrict__ in, float* __restrict__ out) {
    __shared__ float t[32][33];
    int x = blockIdx.x * 32 + threadIdx.x;
    int y = blockIdx.y * 32 + threadIdx.y;
    t[threadIdx.y][threadIdx.x] = in[y * DD + x];
    __syncthreads();
    int xo = blockIdx.y * 32 + threadIdx.x;
    int yo = blockIdx.x * 32 + threadIdx.y;
    out[yo * DD + xo] = t[threadIdx.x][threadIdx.y];
}

// ============ combine + gather (one block per batch, 512 thr) ============
// t==1: no combine, token = SOS. t in [2,64]: reduce partials + beam combine
// (writes position t-1; t==2 is the SOS expansion). doGather=0 skips e gather.
__global__ __launch_bounds__(512) void combine_kernel(
    int t, int doGather, const float* __restrict__ emb)
{
    const int b = blockIdx.x;
    const int tid = threadIdx.x;

    __shared__ float sv[512 * 4];
    __shared__ int   si[512 * 4];
    __shared__ float sM[512], sS[512];
    __shared__ float rowv[KK][4];
    __shared__ int   rowi[KK][4];
    __shared__ float rowlse[KK];
    __shared__ int   s_ntok[4];

    if (t >= 2) {
        const int rloc = tid >> 7;
        const int t2 = tid & 127;
        const int prow = b * KK + rloc;

        float v[4] = {-FLT_MAX, -FLT_MAX, -FLT_MAX, -FLT_MAX};
        int   ix[4] = {0x7fffffff, 0x7fffffff, 0x7fffffff, 0x7fffffff};
        float M = -FLT_MAX, S = 0.f;
        for (int p = t2; p < NT; p += 128) {
            const int base = prow * NT + p;
#pragma unroll
            for (int q = 0; q < 4; q++) ins4(g_pv[base * 4 + q], g_pi[base * 4 + q], v, ix);
            float pm = g_pm[base], ps = g_ps[base];
            if (pm > M) { S = S * expf(M - pm) + ps; M = pm; }
            else        { S += ps * expf(pm - M); }
        }
#pragma unroll
        for (int p = 0; p < 4; p++) { sv[tid * 4 + p] = v[p]; si[tid * 4 + p] = ix[p]; }
        sM[tid] = M; sS[tid] = S;
        __syncthreads();

        for (int off = 64; off > 0; off >>= 1) {
            if (t2 < off) {
                const int o = tid + off;
                float v2[4]; int i2[4];
#pragma unroll
                for (int p = 0; p < 4; p++) { v2[p] = sv[o * 4 + p]; i2[p] = si[o * 4 + p]; }
                float va[4]; int ia[4];
#pragma unroll
                for (int p = 0; p < 4; p++) { va[p] = sv[tid * 4 + p]; ia[p] = si[tid * 4 + p]; }
                merge4(va, ia, v2, i2);
#pragma unroll
                for (int p = 0; p < 4; p++) { sv[tid * 4 + p] = va[p]; si[tid * 4 + p] = ia[p]; }
                float M2 = sM[o], S2 = sS[o];
                float Ma = sM[tid], Sa = sS[tid];
                if (M2 > Ma) { Sa = Sa * expf(Ma - M2) + S2; Ma = M2; }
                else         { Sa += S2 * expf(M2 - Ma); }
                sM[tid] = Ma; sS[tid] = Sa;
            }
            __syncthreads();
        }
        if (t2 == 0) {
#pragma unroll
            for (int p = 0; p < 4; p++) { rowv[rloc][p] = sv[tid * 4 + p]; rowi[rloc][p] = si[tid * 4 + p]; }
            rowlse[rloc] = sM[tid] + logf(sS[tid]);
        }
        __syncthreads();

        const int rp = (t - 1) & 1;
        const int wp = t & 1;
        const int pos = t - 1;

        if (t == 2) {
            if (tid == 0) {
#pragma unroll
                for (int k = 0; k < 4; k++) s_ntok[k] = rowi[0][k];
            }
            __syncthreads();
            if (tid < TT) {
                for (int k = 0; k < 4; k++) {
                    int val = (tid == 0) ? SOS_ : ((tid == 1) ? s_ntok[k] : PAD_);
                    g_seqs[wp][(b * KK + k) * TT + tid] = val;
                }
            }
            if (tid < 4) {
                g_scores2[wp][b * KK + tid] = rowv[0][tid] - rowlse[0];
                g_fin2[wp][b * KK + tid] = (s_ntok[tid] == EOS_) ? 1 : 0;
            }
            __syncthreads();
        } else {
            __shared__ int nbeam[4], nfin[4];
            __shared__ float nsc[4];
            if (tid == 0) {
                float total[16]; int candv[16];
                for (int k = 0; k < 4; k++) {
                    int r = b * KK + k;
                    bool fin = (g_fin2[rp][r] != 0);
                    float lse = rowlse[k];
                    float sc = g_scores2[rp][r];
                    for (int j = 0; j < 4; j++) {
                        float lp; int vtok;
                        if (fin) { lp = (j == 0) ? 0.f : NEG_; vtok = PAD_; }
                        else { lp = rowv[k][j] - lse; vtok = rowi[k][j]; }
                        total[k * 4 + j] = sc + lp;
                        candv[k * 4 + j] = vtok;
                    }
                }
                bool used[16];
                for (int i = 0; i < 16; i++) used[i] = false;
                for (int p = 0; p < 4; p++) {
                    int biq = -1; float bvq = -FLT_MAX;
                    for (int i = 0; i < 16; i++)
                        if (!used[i] && total[i] > bvq) { bvq = total[i]; biq = i; }
                    used[biq] = true;
                    nbeam[p] = biq >> 2;
                    s_ntok[p] = candv[biq];
                    nsc[p] = bvq;
                }
                for (int p = 0; p < 4; p++)
                    nfin[p] = (g_fin2[rp][b * KK + nbeam[p]] != 0 || s_ntok[p] == EOS_) ? 1 : 0;
            }
            __syncthreads();
            if (tid < KK * TT) {
                int k = tid >> 6, ps2 = tid & 63;
                int x = g_seqs[rp][(b * KK + nbeam[k]) * TT + ps2];
                g_seqs[wp][(b * KK + k) * TT + ps2] = (ps2 == pos) ? s_ntok[k] : x;
            }
            if (tid < 4) {
                g_scores2[wp][b * KK + tid] = nsc[tid];
                g_fin2[wp][b * KK + tid] = nfin[tid];
            }
            __syncthreads();
        }
    }

    if (!doGather) return;
#pragma unroll
    for (int k = 0; k < 4; k++) {
        const int tok = (t == 1) ? SOS_ : s_ntok[k];
        g_e[(b * KK + k) * DD + tid] = emb[(size_t)tok * DD + tid];
    }
}

// ============ att1: scores + partial softmax (block per (row, s-quarter)) ============
__global__ __launch_bounds__(256) void att1_kernel(const int* __restrict__ lens)
{
    const int row = blockIdx.x >> 2;
    const int q = blockIdx.x & 3;
    const int b = row >> 2;
    const int tid = threadIdx.x, lane = tid & 31, w = tid >> 5;  // 8 warps

    __shared__ float es[DD];
    __shared__ float sc[128];
    __shared__ float red[10];

    es[tid] = g_e[row * DD + tid];
    es[tid + 256] = g_e[row * DD + tid + 256];
    __syncthreads();

    const int len = lens[b];
    const float scale = 0.04419417382415922f;
    const float* Pb = g_P + ((size_t)b * SS + q * 128) * DD;

    // warp w handles s_loc in [w*16, w*16+16)
    for (int i = 0; i < 16; i++) {
        const int s_loc = w * 16 + i;
        const float* pr = Pb + (size_t)s_loc * DD;
        float acc = 0.f;
#pragma unroll 4
        for (int d = lane; d < DD; d += 32) acc += es[d] * pr[d];
#pragma unroll
        for (int o = 16; o > 0; o >>= 1) acc += __shfl_xor_sync(0xffffffffu, acc, o);
        if (lane == 0) {
            const int sg = q * 128 + s_loc;
            sc[s_loc] = (sg < len) ? acc * scale : NEG_;
        }
    }
    __syncthreads();

    // block max over 128 (threads 0..127 hold one each)
    float x = (tid < 128) ? sc[tid] : -FLT_MAX;
    float m = x;
#pragma unroll
    for (int o = 16; o > 0; o >>= 1) m = fmaxf(m, __shfl_xor_sync(0xffffffffu, m, o));
    if (lane == 0) red[w] = m;
    __syncthreads();
    if (tid == 0) {
        float mm = red[0];
        for (int i = 1; i < 8; i++) mm = fmaxf(mm, red[i]);
        red[8] = mm;
    }
    __syncthreads();
    m = red[8];

    float e = 0.f;
    if (tid < 128) {
        e = expf(x - m);
        g_attp[row * SS + q * 128 + tid] = e;
    }
    float s = e;
#pragma unroll
    for (int o = 16; o > 0; o >>= 1) s += __shfl_xor_sync(0xffffffffu, s, o);
    if (lane == 0) red[w] = s;
    __syncthreads();
    if (tid == 0) {
        float tot = 0.f;
        for (int i = 0; i < 4; i++) tot += red[i];  // only warps 0-3 hold tid<128
        g_am[row * 4 + q] = m;
        g_as[row * 4 + q] = tot;
    }
}

// ============ att2: merge quarters + ctx + h (block per (row, d-quarter)) ============
__global__ __launch_bounds__(128) void att2_kernel(const float* __restrict__ enc)
{
    const int row = blockIdx.x >> 2;
    const int dq = blockIdx.x & 3;
    const int b = row >> 2;
    const int tid = threadIdx.x;
    const int d = dq * 128 + tid;

    float m0 = g_am[row * 4 + 0], m1 = g_am[row * 4 + 1];
    float m2 = g_am[row * 4 + 2], m3 = g_am[row * 4 + 3];
    float mg = fmaxf(fmaxf(m0, m1), fmaxf(m2, m3));
    float f[4];
    f[0] = expf(m0 - mg); f[1] = expf(m1 - mg);
    f[2] = expf(m2 - mg); f[3] = expf(m3 - mg);
    float denom = g_as[row * 4 + 0] * f[0] + g_as[row * 4 + 1] * f[1]
                + g_as[row * 4 + 2] * f[2] + g_as[row * 4 + 3] * f[3];
    const float inv = 1.0f / denom;

    __shared__ float ap[128];
    float c = 0.f;
#pragma unroll
    for (int q = 0; q < 4; q++) {
        __syncthreads();
        ap[tid] = g_attp[row * SS + q * 128 + tid];
        __syncthreads();
        const float* er = enc + ((size_t)b * SS + q * 128) * DD + d;
        float cq = 0.f;
#pragma unroll 4
        for (int s = 0; s < 128; s++) cq += ap[s] * er[(size_t)s * DD];
        c += cq * f[q];
    }
    g_h[row * DD + d] = g_e[row * DD + d] + c * inv;
}

// ---- final: argmax beam per batch ----
__global__ void finalize_kernel(float* out, int out_size, int srcbuf) {
    const int b = blockIdx.x, tid = threadIdx.x;  // 64 threads
    __shared__ int bbk;
    __shared__ float bbs;
    if (tid == 0) {
        int bi = 0; float bv = g_scores2[srcbuf][b * KK];
        for (int k = 1; k < 4; k++) {
            if (g_scores2[srcbuf][b * KK + k] > bv) { bv = g_scores2[srcbuf][b * KK + k]; bi = k; }
        }
        bbk = bi; bbs = bv;
    }
    __syncthreads();
    if (out_size == BB) {
        if (tid == 0) out[b] = bbs;
        return;
    }
    int idx = b * TT + tid;
    if (idx < out_size)
        out[idx] = (float)g_seqs[srcbuf][(b * KK + bbk) * TT + tid];
    if (tid == 0 && BB * TT + b < out_size)
        out[BB * TT + b] = bbs;
}

// ============ host launcher ============
extern "C" void kernel_launch(void* const* d_in, const int* in_sizes, int n_in,
                              void* d_out, int out_size)
{
    const float* enc = (const float*)d_in[0];
    const int*   lens = (const int*)d_in[1];
    const float* emb = (const float*)d_in[2];
    const float* Wq  = (const float*)d_in[3];
    const float* Wk  = (const float*)d_in[4];
    const float* Wfc = (const float*)d_in[5];
    const float* bfc = (const float*)d_in[6];

    float *p_encK, *p_P, *p_WqT, *p_h;
    cudaGetSymbolAddress((void**)&p_encK, g_encK);
    cudaGetSymbolAddress((void**)&p_P, g_P);
    cudaGetSymbolAddress((void**)&p_WqT, g_WqT);
    cudaGetSymbolAddress((void**)&p_h, g_h);

    // encK = enc @ W_k
    {
        dim3 grid(DD / 64, (BB * SS) / 64);
        gemm2_kernel<false><<<grid, 128>>>(enc, Wk, nullptr, p_encK, BB * SS, DD, DD);
    }
    // WqT; P = encK @ Wq^T
    transpose_kernel<<<dim3(16, 16), dim3(32, 32)>>>(Wq, p_WqT);
    {
        dim3 grid(DD / 64, (BB * SS) / 64);
        gemm2_kernel<false><<<grid, 128>>>(p_encK, p_WqT, nullptr, p_P, BB * SS, DD, DD);
    }

    // t=1: SOS gather + attention + logits
    combine_kernel<<<BB, 512>>>(1, 1, emb);
    att1_kernel<<<RR * 4, 256>>>(lens);
    att2_kernel<<<RR * 4, 128>>>(enc);
    gemm2_kernel<true><<<dim3(NT, 1), 128>>>(p_h, Wfc, bfc, nullptr, RR, VV, DD);

    // t=2..63
    for (int t = 2; t < TT; t++) {
        combine_kernel<<<BB, 512>>>(t, 1, emb);
        att1_kernel<<<RR * 4, 256>>>(lens);
        att2_kernel<<<RR * 4, 128>>>(enc);
        gemm2_kernel<true><<<dim3(NT, 1), 128>>>(p_h, Wfc, bfc, nullptr, RR, VV, DD);
    }

    // t=64: final combine only (writes pos 63, parity 0)
    combine_kernel<<<BB, 512>>>(TT, 0, emb);

    finalize_kernel<<<BB, TT>>>((float*)d_out, out_size, 0);
}